// round 15
// baseline (speedup 1.0000x reference)
#include <cuda_runtime.h>
#include <cuda_fp16.h>
#include <math.h>
#include <stdint.h>

#define GG   64
#define NN   1024
#define DIN  128
#define DH   256
#define DOUT 10
#define MT   (GG * NN)          // 65536 nodes
#define NTILES (MT / 128)       // 512 row tiles
#define GRID_B 148
#define KP 136                  // padded row length (halfs)

// ---- scratch (no allocations allowed) ----
__device__ float    g_spart[1024 * DIN]; // per-(graph,slice64) partial of s_g
__device__ float    g_upart[NTILES * DH];// per-tile partial of u
__device__ float    g_invn[MT];          // 1/||x|| per node
__device__ float    g_selfw[MT];         // ||xn||^2 per node
__device__ float    g_w[MT];             // per-node weight
__device__ int      g_cnt[GG];           // per-graph tile arrival counter
__device__ uint32_t g_w1h[DH * DIN / 2]; // W1 fp16 pairs [n][kp]
__device__ uint32_t g_xh[(size_t)MT * 64]; // x fp16 pairs [node][kp] (16MB)

__device__ __forceinline__ uint32_t s2u(const void* p) {
    uint32_t a;
    asm("{ .reg .u64 t; cvta.to.shared.u64 t, %1; cvt.u32.u64 %0, t; }" : "=r"(a) : "l"(p));
    return a;
}

// SMEM layout (bytes) for k_gemm
#define OFF_B1   0        // 256 f
#define OFF_WS   1024     // 128 f
#define OFF_FIN  1536     // 512 B (flag at +508)
#define OFF_A0   2048     // 128*272 = 34816
#define OFF_A1   36864    // 34816
#define OFF_B    71680    // 256*272 = 69632
#define SMEM_TOTAL 141312

// ============================================================
// Kernel 1: slice s_g partials + invn/selfw + x->fp16 pack (c<1024)
//           + W1 -> fp16 packed buffer (c in [1024,1040))
//           + g_cnt reset (c<GG)
// ============================================================
__global__ __launch_bounds__(256) void k_prep1(const float* __restrict__ x,
                                               const float* __restrict__ W1) {
    const int c    = blockIdx.x;
    const int tid  = threadIdx.x;

    if (c >= 1024) {                       // W1 conversion: 16 CTAs x 4 kp
        const int kb = c - 1024;
        #pragma unroll
        for (int i = 0; i < 4; i++) {
            const int kp = kb * 4 + i;
            __half2 hp = __floats2half2_rn(W1[(2 * kp) * DH + tid],
                                           W1[(2 * kp + 1) * DH + tid]);
            g_w1h[tid * 64 + kp] = *(uint32_t*)&hp;
        }
        return;
    }

    const int g    = c >> 4;
    const int sl   = c & 15;
    const int w    = tid >> 5;
    const int lane = tid & 31;

    if (c < GG && tid == 0) g_cnt[c] = 0;

    __shared__ float spart[8][DIN];

    float s0 = 0.f, s1 = 0.f, s2 = 0.f, s3 = 0.f;
    const int base = g * NN + sl * 64 + w * 8;
    #pragma unroll
    for (int r = 0; r < 8; r += 2) {
        const int na = base + r, nb = base + r + 1;
        const float4 va = *(const float4*)(x + (size_t)na * DIN + lane * 4);
        const float4 vb = *(const float4*)(x + (size_t)nb * DIN + lane * 4);
        float sqa = va.x * va.x + va.y * va.y + va.z * va.z + va.w * va.w;
        float sqb = vb.x * vb.x + vb.y * vb.y + vb.z * vb.z + vb.w * vb.w;
        #pragma unroll
        for (int o = 16; o > 0; o >>= 1) {
            sqa += __shfl_xor_sync(0xffffffffu, sqa, o);
            sqb += __shfl_xor_sync(0xffffffffu, sqb, o);
        }
        const float ia = rsqrtf(sqa + 1e-24f);
        const float ib = rsqrtf(sqb + 1e-24f);
        if (lane == 0) {
            g_invn[na] = ia;  g_selfw[na] = sqa * ia * ia;
            g_invn[nb] = ib;  g_selfw[nb] = sqb * ib * ib;
        }
        s0 += ia * va.x + ib * vb.x;
        s1 += ia * va.y + ib * vb.y;
        s2 += ia * va.z + ib * vb.z;
        s3 += ia * va.w + ib * vb.w;
        __half2 a0 = __floats2half2_rn(va.x, va.y);
        __half2 a1 = __floats2half2_rn(va.z, va.w);
        __half2 c0 = __floats2half2_rn(vb.x, vb.y);
        __half2 c1 = __floats2half2_rn(vb.z, vb.w);
        *(uint2*)(g_xh + (size_t)na * 64 + lane * 2) =
            make_uint2(*(uint32_t*)&a0, *(uint32_t*)&a1);
        *(uint2*)(g_xh + (size_t)nb * 64 + lane * 2) =
            make_uint2(*(uint32_t*)&c0, *(uint32_t*)&c1);
    }
    spart[w][lane * 4 + 0] = s0;
    spart[w][lane * 4 + 1] = s1;
    spart[w][lane * 4 + 2] = s2;
    spart[w][lane * 4 + 3] = s3;
    __syncthreads();
    if (tid < DIN) {
        float s = 0.f;
        #pragma unroll
        for (int i = 0; i < 8; i++) s += spart[i][tid];
        g_spart[c * DIN + tid] = s;
    }
}

// ============================================================
// Kernel 2: per-node weight  w = invn*(x.s_g) - selfw
// grid = 512 CTAs x 256 threads (2 threads per node, xh L2-hot)
// ============================================================
__global__ __launch_bounds__(256) void k_prepw() {
    const int c   = blockIdx.x;            // 0..511
    const int g   = c >> 3;
    const int tid = threadIdx.x;

    __shared__ float s_sh[DIN];
    if (tid < DIN) {
        float ss = 0.f;
        #pragma unroll
        for (int sl = 0; sl < 16; sl++)
            ss += g_spart[(g * 16 + sl) * DIN + tid];
        s_sh[tid] = ss;
    }
    __syncthreads();

    const int node = c * 128 + (tid >> 1);
    const int hh   = tid & 1;
    const uint2* xp = (const uint2*)(g_xh + (size_t)node * 64) + hh * 16;
    const float* sp = s_sh + hh * 64;
    float acc = 0.f;
    #pragma unroll
    for (int j = 0; j < 16; j++) {
        const uint2 v = xp[j];
        const float2 f0 = __half22float2(*(const __half2*)&v.x);
        const float2 f1 = __half22float2(*(const __half2*)&v.y);
        acc += f0.x * sp[j * 4] + f0.y * sp[j * 4 + 1]
             + f1.x * sp[j * 4 + 2] + f1.y * sp[j * 4 + 3];
    }
    acc += __shfl_xor_sync(0xffffffffu, acc, 1);
    if (hh == 0) g_w[node] = g_invn[node] * acc - g_selfw[node];
}

// ============================================================
// Kernel 3: persistent HMMA GEMM, pure pipeline tile loop.
//   A tiles prepacked fp16 via double-buffered cp.async.
//   All fences/atomics/finals deferred to a post-loop phase.
// ============================================================
__global__ __launch_bounds__(512, 1) void k_gemm(const float* __restrict__ b1,
                                                 const float* __restrict__ W2,
                                                 const float* __restrict__ b2,
                                                 float* __restrict__ out) {
    extern __shared__ __align__(16) char sm[];
    const uint32_t sb = s2u(sm);
    const int tid  = threadIdx.x;
    const int lane = tid & 31;
    const int wid  = tid >> 5;
    const int wm   = wid >> 3;   // 0..1
    const int wn   = wid & 7;    // 0..7

    float* b1s  = (float*)(sm + OFF_B1);
    float* ws   = (float*)(sm + OFF_WS);
    float* fin  = (float*)(sm + OFF_FIN);
    int*   flag = (int*)(sm + OFF_FIN + 508);
    __shared__ float red_s[16][32];

    if (tid < 256) b1s[tid] = b1[tid];

    // ---- prologue: prefetch first A tile ----
    {
        const char* src = (const char*)(g_xh + (size_t)blockIdx.x * 128 * 64);
        #pragma unroll
        for (int j = 0; j < 4; j++) {
            const int i2 = tid + 512 * j;
            const int row = i2 >> 4, ck = i2 & 15;
            asm volatile("cp.async.ca.shared.global [%0], [%1], 16;"
                         :: "r"(sb + OFF_A0 + row * 272 + ck * 16),
                            "l"(src + row * 256 + ck * 16));
        }
        asm volatile("cp.async.commit_group;");
    }

    // ---- load prepacked W1 fp16 into SMEM (padded rows) ----
    {
        uint32_t* bsm = (uint32_t*)(sm + OFF_B);
        const int n0 = tid >> 2;
        const int kh = (tid & 3) * 16;
        #pragma unroll
        for (int pass = 0; pass < 2; pass++) {
            const int n = pass * 128 + n0;
            const uint4* src = (const uint4*)(g_w1h + n * 64 + kh);
            uint4* dst = (uint4*)(bsm + n * (KP / 2) + kh);
            #pragma unroll
            for (int j = 0; j < 4; j++) dst[j] = src[j];
        }
    }

    // ldmatrix lane offsets (element units)
    const int arow_l = (lane & 7) + ((lane >> 3) & 1) * 8;
    const int acol_l = ((lane >> 4) & 1) * 8;
    const int aoff0  = (wm * 64 + arow_l) * KP + acol_l;
    const int brow_l = (lane & 7) + (lane >> 4) * 8;
    const int bcol_l = ((lane >> 3) & 1) * 8;
    const int boff0  = (wn * 32 + brow_l) * KP + bcol_l;

    // ================= pure pipeline tile loop =================
    int p = 0;
    for (int t = blockIdx.x; t < NTILES; t += GRID_B) {
        const int m0 = t * 128;

        if (tid < 128) ws[tid] = g_w[m0 + tid];

        if (t + GRID_B < NTILES) {
            const uint32_t dst = sb + (p ? OFF_A0 : OFF_A1);
            const char* src = (const char*)(g_xh + (size_t)(t + GRID_B) * 128 * 64);
            #pragma unroll
            for (int j = 0; j < 4; j++) {
                const int i2 = tid + 512 * j;
                const int row = i2 >> 4, ck = i2 & 15;
                asm volatile("cp.async.ca.shared.global [%0], [%1], 16;"
                             :: "r"(dst + row * 272 + ck * 16),
                                "l"(src + row * 256 + ck * 16));
            }
        }
        asm volatile("cp.async.commit_group;");
        asm volatile("cp.async.wait_group 1;");
        __syncthreads();

        float acc[4][4][4];
        #pragma unroll
        for (int mi = 0; mi < 4; mi++)
            #pragma unroll
            for (int ni = 0; ni < 4; ni++)
                #pragma unroll
                for (int q = 0; q < 4; q++) acc[mi][ni][q] = 0.f;

        {
            const uint32_t ab = sb + (p ? OFF_A1 : OFF_A0);
            const uint32_t bb = sb + OFF_B;
            #pragma unroll
            for (int kc = 0; kc < 8; kc++) {
                uint32_t af[4][4];
                #pragma unroll
                for (int mi = 0; mi < 4; mi++) {
                    const uint32_t addr = ab + 2u * (aoff0 + mi * 16 * KP + kc * 16);
                    asm volatile(
                        "ldmatrix.sync.aligned.m8n8.x4.shared.b16 {%0,%1,%2,%3}, [%4];"
                        : "=r"(af[mi][0]), "=r"(af[mi][1]), "=r"(af[mi][2]), "=r"(af[mi][3])
                        : "r"(addr));
                }
                uint32_t bf[2][4];
                #pragma unroll
                for (int n2 = 0; n2 < 2; n2++) {
                    const uint32_t addr = bb + 2u * (boff0 + n2 * 16 * KP + kc * 16);
                    asm volatile(
                        "ldmatrix.sync.aligned.m8n8.x4.shared.b16 {%0,%1,%2,%3}, [%4];"
                        : "=r"(bf[n2][0]), "=r"(bf[n2][1]), "=r"(bf[n2][2]), "=r"(bf[n2][3])
                        : "r"(addr));
                }
                #pragma unroll
                for (int mi = 0; mi < 4; mi++)
                    #pragma unroll
                    for (int ni = 0; ni < 4; ni++) {
                        const int n2 = ni >> 1, sel = (ni & 1) * 2;
                        asm volatile(
                            "mma.sync.aligned.m16n8k16.row.col.f32.f16.f16.f32 "
                            "{%0,%1,%2,%3}, {%4,%5,%6,%7}, {%8,%9}, {%0,%1,%2,%3};"
                            : "+f"(acc[mi][ni][0]), "+f"(acc[mi][ni][1]),
                              "+f"(acc[mi][ni][2]), "+f"(acc[mi][ni][3])
                            : "r"(af[mi][0]), "r"(af[mi][1]), "r"(af[mi][2]), "r"(af[mi][3]),
                              "r"(bf[n2][sel]), "r"(bf[n2][sel + 1]));
                    }
            }
        }

        // ---- epilogue: +b1, relu, *w_m, column reduce ----
        float p0[4], p1[4];
        #pragma unroll
        for (int ni = 0; ni < 4; ni++) { p0[ni] = 0.f; p1[ni] = 0.f; }
        #pragma unroll
        for (int mi = 0; mi < 4; mi++) {
            const float w0 = ws[wm * 64 + mi * 16 + (lane >> 2)];
            const float w1 = ws[wm * 64 + mi * 16 + (lane >> 2) + 8];
            #pragma unroll
            for (int ni = 0; ni < 4; ni++) {
                const int cc = wn * 32 + ni * 8 + (lane & 3) * 2;
                const float bb0 = b1s[cc], bb1 = b1s[cc + 1];
                float h;
                h = acc[mi][ni][0] + bb0; h = h > 0.f ? h : 0.f; p0[ni] += w0 * h;
                h = acc[mi][ni][2] + bb0; h = h > 0.f ? h : 0.f; p0[ni] += w1 * h;
                h = acc[mi][ni][1] + bb1; h = h > 0.f ? h : 0.f; p1[ni] += w0 * h;
                h = acc[mi][ni][3] + bb1; h = h > 0.f ? h : 0.f; p1[ni] += w1 * h;
            }
        }
        #pragma unroll
        for (int ni = 0; ni < 4; ni++) {
            #pragma unroll
            for (int o = 4; o < 32; o <<= 1) {
                p0[ni] += __shfl_xor_sync(0xffffffffu, p0[ni], o);
                p1[ni] += __shfl_xor_sync(0xffffffffu, p1[ni], o);
            }
        }
        if (lane < 4) {
            #pragma unroll
            for (int ni = 0; ni < 4; ni++) {
                red_s[wid][ni * 8 + lane * 2]     = p0[ni];
                red_s[wid][ni * 8 + lane * 2 + 1] = p1[ni];
            }
        }
        __syncthreads();
        if (tid < 256) {
            const int wn_ = tid >> 5, cc = tid & 31;
            g_upart[(size_t)t * DH + tid] = red_s[wn_][cc] + red_s[8 + wn_][cc];
        }
        __syncthreads();
        p ^= 1;
    }

    // ================= post-loop: release + finals =================
    __threadfence();
    for (int t = blockIdx.x; t < NTILES; t += GRID_B) {
        const int gph = t >> 3;
        if (tid == 0) {
            const int old = atomicAdd(&g_cnt[gph], 1);
            *flag = (old == 7) ? 1 : 0;
        }
        __syncthreads();
        if (*flag) {
            if (tid == 0) __threadfence();
            __syncthreads();
            float pc[DOUT];
            if (tid < 256) {
                float u = 0.f;
                #pragma unroll
                for (int r = 0; r < 8; r++)
                    u += __ldcg(&g_upart[(size_t)(gph * 8 + r) * DH + tid]);
                u *= (1.0f / NN);
                #pragma unroll
                for (int c2 = 0; c2 < DOUT; c2++) pc[c2] = u * W2[tid * DOUT + c2];
                #pragma unroll
                for (int c2 = 0; c2 < DOUT; c2++)
                    #pragma unroll
                    for (int o = 16; o > 0; o >>= 1)
                        pc[c2] += __shfl_xor_sync(0xffffffffu, pc[c2], o);
                if (lane == 0) {
                    #pragma unroll
                    for (int c2 = 0; c2 < DOUT; c2++) fin[wid * DOUT + c2] = pc[c2];
                }
            }
            __syncthreads();
            if (tid < DOUT) {
                float v = b2[tid];
                #pragma unroll
                for (int ww = 0; ww < 8; ww++) v += fin[ww * DOUT + tid];
                fin[96 + tid] = v;
            }
            __syncthreads();
            if (tid == 0) {
                float mx = fin[96];
                #pragma unroll
                for (int c2 = 1; c2 < DOUT; c2++) mx = fmaxf(mx, fin[96 + c2]);
                float se = 0.f;
                #pragma unroll
                for (int c2 = 0; c2 < DOUT; c2++) se += expf(fin[96 + c2] - mx);
                fin[110] = mx;
                fin[111] = logf(se);
            }
            __syncthreads();
            if (tid < DOUT)
                out[gph * DOUT + tid] = fin[96 + tid] - fin[110] - fin[111];
        }
        __syncthreads();
    }
}

// ============================================================
extern "C" void kernel_launch(void* const* d_in, const int* in_sizes, int n_in,
                              void* d_out, int out_size) {
    const float* x  = (const float*)d_in[0];
    // d_in[1] = batch (int64) — sorted equal-sized graphs, not needed
    const float* W1 = (const float*)d_in[2];
    const float* b1 = (const float*)d_in[3];
    const float* W2 = (const float*)d_in[4];
    const float* b2 = (const float*)d_in[5];
    float* out = (float*)d_out;

    cudaFuncSetAttribute(k_gemm, cudaFuncAttributeMaxDynamicSharedMemorySize, SMEM_TOTAL);

    k_prep1<<<1040, 256>>>(x, W1);
    k_prepw<<<512, 256>>>();
    k_gemm<<<GRID_B, 512, SMEM_TOTAL>>>(b1, W2, b2, out);
}

// round 16
// speedup vs baseline: 1.1894x; 1.1894x over previous
#include <cuda_runtime.h>
#include <cuda_fp16.h>
#include <math.h>
#include <stdint.h>

#define GG   64
#define NN   1024
#define DIN  128
#define DH   256
#define DOUT 10
#define MT   (GG * NN)          // 65536 nodes
#define NTILES (MT / 128)       // 512 row tiles
#define GRID_B 148
#define KP 136                  // padded row length (halfs)

// ---- scratch (no allocations allowed) ----
__device__ float    g_spart[1024 * DIN]; // per-(graph,slice64) partial of s_g
__device__ float    g_upart[NTILES * DH];// per-tile partial of u
__device__ int      g_cnt[GG];           // per-graph tile arrival counter
__device__ uint32_t g_w1h[DH * DIN / 2]; // W1 fp16 pairs [n][kp]

__device__ __forceinline__ uint32_t s2u(const void* p) {
    uint32_t a;
    asm("{ .reg .u64 t; cvta.to.shared.u64 t, %1; cvt.u32.u64 %0, t; }" : "=r"(a) : "l"(p));
    return a;
}

// SMEM layout (bytes)
#define OFF_B1   0        // 256 f
#define OFF_WS   1024     // 128 f
#define OFF_SALL 1536     // 4*128 f = 2048
#define OFF_FIN  3584     // 512 B (flag at +508)
#define OFF_A    4096     // 128*272 = 34816
#define OFF_B    38912    // 256*272 = 69632
#define SMEM_TOTAL 108544

// ============================================================
// Kernel 1: partial s_g per (graph, slice of 64 nodes) (c<1024)
//           + W1 -> fp16 packed buffer (c in [1024,1040))
//           + g_cnt reset (c<GG)
// ============================================================
__global__ __launch_bounds__(256) void k_prep1(const float* __restrict__ x,
                                               const float* __restrict__ W1) {
    const int c    = blockIdx.x;
    const int tid  = threadIdx.x;

    if (c >= 1024) {                       // W1 conversion: 16 CTAs x 4 kp
        const int kb = c - 1024;
        #pragma unroll
        for (int i = 0; i < 4; i++) {
            const int kp = kb * 4 + i;
            __half2 hp = __floats2half2_rn(W1[(2 * kp) * DH + tid],
                                           W1[(2 * kp + 1) * DH + tid]);
            g_w1h[tid * 64 + kp] = *(uint32_t*)&hp;
        }
        return;
    }

    const int g    = c >> 4;
    const int sl   = c & 15;
    const int w    = tid >> 5;
    const int lane = tid & 31;

    if (c < GG && tid == 0) g_cnt[c] = 0;

    __shared__ float spart[8][DIN];

    float s0 = 0.f, s1 = 0.f, s2 = 0.f, s3 = 0.f;
    const int base = g * NN + sl * 64 + w * 8;
    #pragma unroll
    for (int r = 0; r < 8; r += 2) {
        const float4 va = *(const float4*)(x + (size_t)(base + r)     * DIN + lane * 4);
        const float4 vb = *(const float4*)(x + (size_t)(base + r + 1) * DIN + lane * 4);
        float sqa = va.x * va.x + va.y * va.y + va.z * va.z + va.w * va.w;
        float sqb = vb.x * vb.x + vb.y * vb.y + vb.z * vb.z + vb.w * vb.w;
        #pragma unroll
        for (int o = 16; o > 0; o >>= 1) {
            sqa += __shfl_xor_sync(0xffffffffu, sqa, o);
            sqb += __shfl_xor_sync(0xffffffffu, sqb, o);
        }
        const float ia = rsqrtf(sqa + 1e-24f);
        const float ib = rsqrtf(sqb + 1e-24f);
        s0 += ia * va.x + ib * vb.x;
        s1 += ia * va.y + ib * vb.y;
        s2 += ia * va.z + ib * vb.z;
        s3 += ia * va.w + ib * vb.w;
    }
    spart[w][lane * 4 + 0] = s0;
    spart[w][lane * 4 + 1] = s1;
    spart[w][lane * 4 + 2] = s2;
    spart[w][lane * 4 + 3] = s3;
    __syncthreads();
    if (tid < DIN) {
        float s = 0.f;
        #pragma unroll
        for (int i = 0; i < 8; i++) s += spart[i][tid];
        g_spart[c * DIN + tid] = s;
    }
}

// ============================================================
// Kernel 2: persistent HMMA GEMM  h = relu(X@W1+b1) + epilogue
//   single-pass fp16 (A converted in-loop), fp32 accumulate.
//   s_g hoisted to a single pre-loop phase (<=4 graphs per CTA).
//   Last CTA per graph runs (u/N)@W2+b2 + log-softmax inline.
// ============================================================
__global__ __launch_bounds__(512, 1) void k_gemm(const float* __restrict__ x,
                                                 const float* __restrict__ b1,
                                                 const float* __restrict__ W2,
                                                 const float* __restrict__ b2,
                                                 float* __restrict__ out) {
    extern __shared__ __align__(16) char sm[];
    const uint32_t sb = s2u(sm);
    const int tid  = threadIdx.x;
    const int lane = tid & 31;
    const int wid  = tid >> 5;
    const int wm   = wid >> 3;   // 0..1
    const int wn   = wid & 7;    // 0..7
    const int cb   = blockIdx.x;

    float* b1s   = (float*)(sm + OFF_B1);
    float* ws    = (float*)(sm + OFF_WS);
    float* s_all = (float*)(sm + OFF_SALL);   // [4][128]
    float* fin   = (float*)(sm + OFF_FIN);
    int*   flag  = (int*)(sm + OFF_FIN + 508);
    __shared__ float red_s[16][32];

    if (tid < 256) b1s[tid] = b1[tid];

    // ---- load prepacked W1 fp16 into SMEM (padded rows) ----
    {
        uint32_t* bsm = (uint32_t*)(sm + OFF_B);
        const int n0 = tid >> 2;
        const int kh = (tid & 3) * 16;
        #pragma unroll
        for (int pass = 0; pass < 2; pass++) {
            const int n = pass * 128 + n0;
            const uint4* src = (const uint4*)(g_w1h + n * 64 + kh);
            uint4* dst = (uint4*)(bsm + n * (KP / 2) + kh);
            #pragma unroll
            for (int j = 0; j < 4; j++) dst[j] = src[j];
        }
    }

    // ---- pre-loop: s_g for all (<=4) graphs this CTA will touch ----
    {
        const int i = tid >> 7;            // 0..3  (tile index within CTA)
        const int d = tid & 127;
        const int t = cb + i * GRID_B;
        if (t < NTILES) {
            const int gph = t >> 3;
            float ssum = 0.f;
            #pragma unroll
            for (int sl = 0; sl < 16; sl++)
                ssum += g_spart[(gph * 16 + sl) * DIN + d];
            s_all[i * 128 + d] = ssum;
        }
    }
    __syncthreads();

    // ldmatrix lane offsets (element units)
    const int arow_l = (lane & 7) + ((lane >> 3) & 1) * 8;
    const int acol_l = ((lane >> 4) & 1) * 8;
    const int aoff0  = (wm * 64 + arow_l) * KP + acol_l;
    const int brow_l = (lane & 7) + (lane >> 4) * 8;
    const int bcol_l = ((lane >> 3) & 1) * 8;
    const int boff0  = (wn * 32 + brow_l) * KP + bcol_l;

    int it = 0;
    for (int t = cb; t < NTILES; t += GRID_B, it++) {
        const int m0  = t * 128;
        const int gph = t >> 3;

        // ---- convert A tile (warp owns rows wid*8..+7) + compute w_m ----
        {
            uint32_t* ahi = (uint32_t*)(sm + OFF_A);
            const float4 sv = *(const float4*)(s_all + it * 128 + lane * 4);
            #pragma unroll
            for (int r = 0; r < 8; r++) {
                const int row = wid * 8 + r;
                const float4 v = *(const float4*)(x + (size_t)(m0 + row) * DIN + lane * 4);
                float sq = v.x * v.x + v.y * v.y + v.z * v.z + v.w * v.w;
                float dt = v.x * sv.x + v.y * sv.y + v.z * sv.z + v.w * sv.w;
                #pragma unroll
                for (int o = 16; o > 0; o >>= 1) {
                    sq += __shfl_xor_sync(0xffffffffu, sq, o);
                    dt += __shfl_xor_sync(0xffffffffu, dt, o);
                }
                __half2 hp0 = __floats2half2_rn(v.x, v.y);
                __half2 hp1 = __floats2half2_rn(v.z, v.w);
                const int o = row * (KP / 2) + lane * 2;
                ahi[o]     = *(uint32_t*)&hp0;
                ahi[o + 1] = *(uint32_t*)&hp1;
                if (lane == 0) {
                    const float invn = rsqrtf(sq + 1e-24f);
                    ws[row] = invn * dt - sq * invn * invn;
                }
            }
        }
        __syncthreads();

        // ---- single-pass MMA into fp32 acc ----
        float acc[4][4][4];
        #pragma unroll
        for (int mi = 0; mi < 4; mi++)
            #pragma unroll
            for (int ni = 0; ni < 4; ni++)
                #pragma unroll
                for (int q = 0; q < 4; q++) acc[mi][ni][q] = 0.f;

        {
            const uint32_t ab = sb + OFF_A;
            const uint32_t bb = sb + OFF_B;
            #pragma unroll
            for (int kc = 0; kc < 8; kc++) {
                uint32_t af[4][4];
                #pragma unroll
                for (int mi = 0; mi < 4; mi++) {
                    const uint32_t addr = ab + 2u * (aoff0 + mi * 16 * KP + kc * 16);
                    asm volatile(
                        "ldmatrix.sync.aligned.m8n8.x4.shared.b16 {%0,%1,%2,%3}, [%4];"
                        : "=r"(af[mi][0]), "=r"(af[mi][1]), "=r"(af[mi][2]), "=r"(af[mi][3])
                        : "r"(addr));
                }
                uint32_t bf[2][4];
                #pragma unroll
                for (int n2 = 0; n2 < 2; n2++) {
                    const uint32_t addr = bb + 2u * (boff0 + n2 * 16 * KP + kc * 16);
                    asm volatile(
                        "ldmatrix.sync.aligned.m8n8.x4.shared.b16 {%0,%1,%2,%3}, [%4];"
                        : "=r"(bf[n2][0]), "=r"(bf[n2][1]), "=r"(bf[n2][2]), "=r"(bf[n2][3])
                        : "r"(addr));
                }
                #pragma unroll
                for (int mi = 0; mi < 4; mi++)
                    #pragma unroll
                    for (int ni = 0; ni < 4; ni++) {
                        const int n2 = ni >> 1, sel = (ni & 1) * 2;
                        asm volatile(
                            "mma.sync.aligned.m16n8k16.row.col.f32.f16.f16.f32 "
                            "{%0,%1,%2,%3}, {%4,%5,%6,%7}, {%8,%9}, {%0,%1,%2,%3};"
                            : "+f"(acc[mi][ni][0]), "+f"(acc[mi][ni][1]),
                              "+f"(acc[mi][ni][2]), "+f"(acc[mi][ni][3])
                            : "r"(af[mi][0]), "r"(af[mi][1]), "r"(af[mi][2]), "r"(af[mi][3]),
                              "r"(bf[n2][sel]), "r"(bf[n2][sel + 1]));
                    }
            }
        }

        // ---- epilogue: +b1, relu, *w_m, column reduce ----
        float p0[4], p1[4];
        #pragma unroll
        for (int ni = 0; ni < 4; ni++) { p0[ni] = 0.f; p1[ni] = 0.f; }
        #pragma unroll
        for (int mi = 0; mi < 4; mi++) {
            const float w0 = ws[wm * 64 + mi * 16 + (lane >> 2)];
            const float w1 = ws[wm * 64 + mi * 16 + (lane >> 2) + 8];
            #pragma unroll
            for (int ni = 0; ni < 4; ni++) {
                const int cc = wn * 32 + ni * 8 + (lane & 3) * 2;
                const float bb0 = b1s[cc], bb1 = b1s[cc + 1];
                float h;
                h = acc[mi][ni][0] + bb0; h = h > 0.f ? h : 0.f; p0[ni] += w0 * h;
                h = acc[mi][ni][2] + bb0; h = h > 0.f ? h : 0.f; p0[ni] += w1 * h;
                h = acc[mi][ni][1] + bb1; h = h > 0.f ? h : 0.f; p1[ni] += w0 * h;
                h = acc[mi][ni][3] + bb1; h = h > 0.f ? h : 0.f; p1[ni] += w1 * h;
            }
        }
        #pragma unroll
        for (int ni = 0; ni < 4; ni++) {
            #pragma unroll
            for (int o = 4; o < 32; o <<= 1) {
                p0[ni] += __shfl_xor_sync(0xffffffffu, p0[ni], o);
                p1[ni] += __shfl_xor_sync(0xffffffffu, p1[ni], o);
            }
        }
        if (lane < 4) {
            #pragma unroll
            for (int ni = 0; ni < 4; ni++) {
                red_s[wid][ni * 8 + lane * 2]     = p0[ni];
                red_s[wid][ni * 8 + lane * 2 + 1] = p1[ni];
            }
        }
        __syncthreads();
        if (tid < 256) {
            const int wn_ = tid >> 5, cc = tid & 31;
            g_upart[(size_t)t * DH + tid] = red_s[wn_][cc] + red_s[8 + wn_][cc];
        }

        // ---- release; last CTA of this graph runs the final ----
        __threadfence();
        __syncthreads();
        if (tid == 0) {
            const int old = atomicAdd(&g_cnt[gph], 1);
            *flag = (old == 7) ? 1 : 0;
        }
        __syncthreads();

        if (*flag) {
            if (tid == 0) __threadfence();
            __syncthreads();
            float pc[DOUT];
            if (tid < 256) {
                float u = 0.f;
                #pragma unroll
                for (int r = 0; r < 8; r++)
                    u += __ldcg(&g_upart[(size_t)(gph * 8 + r) * DH + tid]);
                u *= (1.0f / NN);
                #pragma unroll
                for (int c2 = 0; c2 < DOUT; c2++) pc[c2] = u * W2[tid * DOUT + c2];
                #pragma unroll
                for (int c2 = 0; c2 < DOUT; c2++)
                    #pragma unroll
                    for (int o = 16; o > 0; o >>= 1)
                        pc[c2] += __shfl_xor_sync(0xffffffffu, pc[c2], o);
                if (lane == 0) {
                    #pragma unroll
                    for (int c2 = 0; c2 < DOUT; c2++) fin[wid * DOUT + c2] = pc[c2];
                }
            }
            __syncthreads();
            if (tid < DOUT) {
                float v = b2[tid];
                #pragma unroll
                for (int ww = 0; ww < 8; ww++) v += fin[ww * DOUT + tid];
                fin[96 + tid] = v;
            }
            __syncthreads();
            if (tid == 0) {
                float mx = fin[96];
                #pragma unroll
                for (int c2 = 1; c2 < DOUT; c2++) mx = fmaxf(mx, fin[96 + c2]);
                float se = 0.f;
                #pragma unroll
                for (int c2 = 0; c2 < DOUT; c2++) se += expf(fin[96 + c2] - mx);
                fin[110] = mx;
                fin[111] = logf(se);
            }
            __syncthreads();
            if (tid < DOUT)
                out[gph * DOUT + tid] = fin[96 + tid] - fin[110] - fin[111];
        }
        __syncthreads();
    }
}

// ============================================================
extern "C" void kernel_launch(void* const* d_in, const int* in_sizes, int n_in,
                              void* d_out, int out_size) {
    const float* x  = (const float*)d_in[0];
    // d_in[1] = batch (int64) — sorted equal-sized graphs, not needed
    const float* W1 = (const float*)d_in[2];
    const float* b1 = (const float*)d_in[3];
    const float* W2 = (const float*)d_in[4];
    const float* b2 = (const float*)d_in[5];
    float* out = (float*)d_out;

    cudaFuncSetAttribute(k_gemm, cudaFuncAttributeMaxDynamicSharedMemorySize, SMEM_TOTAL);

    k_prep1<<<1040, 256>>>(x, W1);
    k_gemm<<<GRID_B, 512, SMEM_TOTAL>>>(x, b1, W2, b2, out);
}

// round 17
// speedup vs baseline: 1.2653x; 1.0638x over previous
#include <cuda_runtime.h>
#include <cuda_fp16.h>
#include <math.h>
#include <stdint.h>

#define GG   64
#define NN   1024
#define DIN  128
#define DH   256
#define DOUT 10
#define MT   (GG * NN)          // 65536 nodes
#define NTILES (MT / 128)       // 512 row tiles
#define GRID_B 148
#define KP 136                  // padded row length (halfs)

// ---- scratch (no allocations allowed) ----
__device__ float    g_spart[1024 * DIN]; // per-(graph,slice64) partial of s_g
__device__ float    g_upart[NTILES * DH];// per-tile partial of u
__device__ int      g_cnt[GG];           // per-graph tile arrival counter
__device__ int      g_tick;              // dynamic tile ticket
__device__ uint32_t g_w1h[DH * DIN / 2]; // W1 fp16 pairs [n][kp]

__device__ __forceinline__ uint32_t s2u(const void* p) {
    uint32_t a;
    asm("{ .reg .u64 t; cvta.to.shared.u64 t, %1; cvt.u32.u64 %0, t; }" : "=r"(a) : "l"(p));
    return a;
}

// SMEM layout (bytes)
#define OFF_B1   0        // 256 f
#define OFF_WS   1024     // 128 f
#define OFF_S    1536     // 128 f
#define OFF_FIN  2048     // 512 B (flag at +508)
#define OFF_A    2560     // 128*272 = 34816
#define OFF_B    37376    // 256*272 = 69632
#define SMEM_TOTAL 107008

// ============================================================
// Kernel 1: partial s_g per (graph, slice of 64 nodes) (c<1024)
//           + W1 -> fp16 packed buffer (c in [1024,1040))
//           + g_cnt / g_tick reset
// ============================================================
__global__ __launch_bounds__(256) void k_prep1(const float* __restrict__ x,
                                               const float* __restrict__ W1) {
    const int c    = blockIdx.x;
    const int tid  = threadIdx.x;

    if (c >= 1024) {                       // W1 conversion: 16 CTAs x 4 kp
        const int kb = c - 1024;
        #pragma unroll
        for (int i = 0; i < 4; i++) {
            const int kp = kb * 4 + i;
            __half2 hp = __floats2half2_rn(W1[(2 * kp) * DH + tid],
                                           W1[(2 * kp + 1) * DH + tid]);
            g_w1h[tid * 64 + kp] = *(uint32_t*)&hp;
        }
        return;
    }

    const int g    = c >> 4;
    const int sl   = c & 15;
    const int w    = tid >> 5;
    const int lane = tid & 31;

    if (c < GG && tid == 0) g_cnt[c] = 0;
    if (c == 0 && tid == 1) g_tick = GRID_B;

    __shared__ float spart[8][DIN];

    float s0 = 0.f, s1 = 0.f, s2 = 0.f, s3 = 0.f;
    const int base = g * NN + sl * 64 + w * 8;
    #pragma unroll
    for (int r = 0; r < 8; r += 2) {
        const float4 va = *(const float4*)(x + (size_t)(base + r)     * DIN + lane * 4);
        const float4 vb = *(const float4*)(x + (size_t)(base + r + 1) * DIN + lane * 4);
        float sqa = va.x * va.x + va.y * va.y + va.z * va.z + va.w * va.w;
        float sqb = vb.x * vb.x + vb.y * vb.y + vb.z * vb.z + vb.w * vb.w;
        #pragma unroll
        for (int o = 16; o > 0; o >>= 1) {
            sqa += __shfl_xor_sync(0xffffffffu, sqa, o);
            sqb += __shfl_xor_sync(0xffffffffu, sqb, o);
        }
        const float ia = rsqrtf(sqa + 1e-24f);
        const float ib = rsqrtf(sqb + 1e-24f);
        s0 += ia * va.x + ib * vb.x;
        s1 += ia * va.y + ib * vb.y;
        s2 += ia * va.z + ib * vb.z;
        s3 += ia * va.w + ib * vb.w;
    }
    spart[w][lane * 4 + 0] = s0;
    spart[w][lane * 4 + 1] = s1;
    spart[w][lane * 4 + 2] = s2;
    spart[w][lane * 4 + 3] = s3;
    __syncthreads();
    if (tid < DIN) {
        float s = 0.f;
        #pragma unroll
        for (int i = 0; i < 8; i++) s += spart[i][tid];
        g_spart[c * DIN + tid] = s;
    }
}

// ============================================================
// Kernel 2: persistent HMMA GEMM with DYNAMIC tile tickets.
//   single-pass fp16 (A converted in-loop), fp32 accumulate.
//   Last CTA per graph runs (u/N)@W2+b2 + log-softmax inline.
// ============================================================
__global__ __launch_bounds__(512, 1) void k_gemm(const float* __restrict__ x,
                                                 const float* __restrict__ b1,
                                                 const float* __restrict__ W2,
                                                 const float* __restrict__ b2,
                                                 float* __restrict__ out) {
    extern __shared__ __align__(16) char sm[];
    const uint32_t sb = s2u(sm);
    const int tid  = threadIdx.x;
    const int lane = tid & 31;
    const int wid  = tid >> 5;
    const int wm   = wid >> 3;   // 0..1
    const int wn   = wid & 7;    // 0..7

    float* b1s  = (float*)(sm + OFF_B1);
    float* ws   = (float*)(sm + OFF_WS);
    float* s_sh = (float*)(sm + OFF_S);
    float* fin  = (float*)(sm + OFF_FIN);
    int*   flag = (int*)(sm + OFF_FIN + 508);
    __shared__ float red_s[16][32];
    __shared__ int   sh_next;

    if (tid < 256) b1s[tid] = b1[tid];

    // ---- load prepacked W1 fp16 into SMEM (padded rows) ----
    {
        uint32_t* bsm = (uint32_t*)(sm + OFF_B);
        const int n0 = tid >> 2;
        const int kh = (tid & 3) * 16;
        #pragma unroll
        for (int pass = 0; pass < 2; pass++) {
            const int n = pass * 128 + n0;
            const uint4* src = (const uint4*)(g_w1h + n * 64 + kh);
            uint4* dst = (uint4*)(bsm + n * (KP / 2) + kh);
            #pragma unroll
            for (int j = 0; j < 4; j++) dst[j] = src[j];
        }
    }

    // ldmatrix lane offsets (element units)
    const int arow_l = (lane & 7) + ((lane >> 3) & 1) * 8;
    const int acol_l = ((lane >> 4) & 1) * 8;
    const int aoff0  = (wm * 64 + arow_l) * KP + acol_l;
    const int brow_l = (lane & 7) + (lane >> 4) * 8;
    const int bcol_l = ((lane >> 3) & 1) * 8;
    const int boff0  = (wn * 32 + brow_l) * KP + bcol_l;

    int t = blockIdx.x;               // first tile is static
    while (t < NTILES) {
        const int m0  = t * 128;
        const int gph = t >> 3;

        // ---- s_g for this tile's graph (reduce 16 slice partials) ----
        if (tid < DIN) {
            float ssum = 0.f;
            #pragma unroll
            for (int sl = 0; sl < 16; sl++)
                ssum += g_spart[(gph * 16 + sl) * DIN + tid];
            s_sh[tid] = ssum;
        }
        __syncthreads();

        // ---- convert A tile (warp owns rows wid*8..+7) + compute w_m ----
        {
            uint32_t* ahi = (uint32_t*)(sm + OFF_A);
            const float4 sv = *(const float4*)(s_sh + lane * 4);
            #pragma unroll
            for (int r = 0; r < 8; r++) {
                const int row = wid * 8 + r;
                const float4 v = *(const float4*)(x + (size_t)(m0 + row) * DIN + lane * 4);
                float sq = v.x * v.x + v.y * v.y + v.z * v.z + v.w * v.w;
                float dt = v.x * sv.x + v.y * sv.y + v.z * sv.z + v.w * sv.w;
                #pragma unroll
                for (int o = 16; o > 0; o >>= 1) {
                    sq += __shfl_xor_sync(0xffffffffu, sq, o);
                    dt += __shfl_xor_sync(0xffffffffu, dt, o);
                }
                __half2 hp0 = __floats2half2_rn(v.x, v.y);
                __half2 hp1 = __floats2half2_rn(v.z, v.w);
                const int o = row * (KP / 2) + lane * 2;
                ahi[o]     = *(uint32_t*)&hp0;
                ahi[o + 1] = *(uint32_t*)&hp1;
                if (lane == 0) {
                    const float invn = rsqrtf(sq + 1e-24f);
                    ws[row] = invn * dt - sq * invn * invn;
                }
            }
        }
        __syncthreads();

        // ---- single-pass MMA into fp32 acc ----
        float acc[4][4][4];
        #pragma unroll
        for (int mi = 0; mi < 4; mi++)
            #pragma unroll
            for (int ni = 0; ni < 4; ni++)
                #pragma unroll
                for (int q = 0; q < 4; q++) acc[mi][ni][q] = 0.f;

        {
            const uint32_t ab = sb + OFF_A;
            const uint32_t bb = sb + OFF_B;
            #pragma unroll
            for (int kc = 0; kc < 8; kc++) {
                uint32_t af[4][4];
                #pragma unroll
                for (int mi = 0; mi < 4; mi++) {
                    const uint32_t addr = ab + 2u * (aoff0 + mi * 16 * KP + kc * 16);
                    asm volatile(
                        "ldmatrix.sync.aligned.m8n8.x4.shared.b16 {%0,%1,%2,%3}, [%4];"
                        : "=r"(af[mi][0]), "=r"(af[mi][1]), "=r"(af[mi][2]), "=r"(af[mi][3])
                        : "r"(addr));
                }
                uint32_t bf[2][4];
                #pragma unroll
                for (int n2 = 0; n2 < 2; n2++) {
                    const uint32_t addr = bb + 2u * (boff0 + n2 * 16 * KP + kc * 16);
                    asm volatile(
                        "ldmatrix.sync.aligned.m8n8.x4.shared.b16 {%0,%1,%2,%3}, [%4];"
                        : "=r"(bf[n2][0]), "=r"(bf[n2][1]), "=r"(bf[n2][2]), "=r"(bf[n2][3])
                        : "r"(addr));
                }
                #pragma unroll
                for (int mi = 0; mi < 4; mi++)
                    #pragma unroll
                    for (int ni = 0; ni < 4; ni++) {
                        const int n2 = ni >> 1, sel = (ni & 1) * 2;
                        asm volatile(
                            "mma.sync.aligned.m16n8k16.row.col.f32.f16.f16.f32 "
                            "{%0,%1,%2,%3}, {%4,%5,%6,%7}, {%8,%9}, {%0,%1,%2,%3};"
                            : "+f"(acc[mi][ni][0]), "+f"(acc[mi][ni][1]),
                              "+f"(acc[mi][ni][2]), "+f"(acc[mi][ni][3])
                            : "r"(af[mi][0]), "r"(af[mi][1]), "r"(af[mi][2]), "r"(af[mi][3]),
                              "r"(bf[n2][sel]), "r"(bf[n2][sel + 1]));
                    }
            }
        }

        // ---- epilogue: +b1, relu, *w_m, column reduce ----
        float p0[4], p1[4];
        #pragma unroll
        for (int ni = 0; ni < 4; ni++) { p0[ni] = 0.f; p1[ni] = 0.f; }
        #pragma unroll
        for (int mi = 0; mi < 4; mi++) {
            const float w0 = ws[wm * 64 + mi * 16 + (lane >> 2)];
            const float w1 = ws[wm * 64 + mi * 16 + (lane >> 2) + 8];
            #pragma unroll
            for (int ni = 0; ni < 4; ni++) {
                const int cc = wn * 32 + ni * 8 + (lane & 3) * 2;
                const float bb0 = b1s[cc], bb1 = b1s[cc + 1];
                float h;
                h = acc[mi][ni][0] + bb0; h = h > 0.f ? h : 0.f; p0[ni] += w0 * h;
                h = acc[mi][ni][2] + bb0; h = h > 0.f ? h : 0.f; p0[ni] += w1 * h;
                h = acc[mi][ni][1] + bb1; h = h > 0.f ? h : 0.f; p1[ni] += w0 * h;
                h = acc[mi][ni][3] + bb1; h = h > 0.f ? h : 0.f; p1[ni] += w1 * h;
            }
        }
        #pragma unroll
        for (int ni = 0; ni < 4; ni++) {
            #pragma unroll
            for (int o = 4; o < 32; o <<= 1) {
                p0[ni] += __shfl_xor_sync(0xffffffffu, p0[ni], o);
                p1[ni] += __shfl_xor_sync(0xffffffffu, p1[ni], o);
            }
        }
        if (lane < 4) {
            #pragma unroll
            for (int ni = 0; ni < 4; ni++) {
                red_s[wid][ni * 8 + lane * 2]     = p0[ni];
                red_s[wid][ni * 8 + lane * 2 + 1] = p1[ni];
            }
        }
        // fetch next ticket; the barrier below publishes both red_s and sh_next
        if (tid == 0) sh_next = atomicAdd(&g_tick, 1);
        __syncthreads();
        if (tid < 256) {
            const int wn_ = tid >> 5, cc = tid & 31;
            g_upart[(size_t)t * DH + tid] = red_s[wn_][cc] + red_s[8 + wn_][cc];
        }

        // ---- release; last CTA of this graph runs the final ----
        __threadfence();
        __syncthreads();
        if (tid == 0) {
            const int old = atomicAdd(&g_cnt[gph], 1);
            *flag = (old == 7) ? 1 : 0;
        }
        __syncthreads();

        if (*flag) {
            if (tid == 0) __threadfence();
            __syncthreads();
            float pc[DOUT];
            if (tid < 256) {
                float u = 0.f;
                #pragma unroll
                for (int r = 0; r < 8; r++)
                    u += __ldcg(&g_upart[(size_t)(gph * 8 + r) * DH + tid]);
                u *= (1.0f / NN);
                #pragma unroll
                for (int c2 = 0; c2 < DOUT; c2++) pc[c2] = u * W2[tid * DOUT + c2];
                #pragma unroll
                for (int c2 = 0; c2 < DOUT; c2++)
                    #pragma unroll
                    for (int o = 16; o > 0; o >>= 1)
                        pc[c2] += __shfl_xor_sync(0xffffffffu, pc[c2], o);
                if (lane == 0) {
                    #pragma unroll
                    for (int c2 = 0; c2 < DOUT; c2++) fin[wid * DOUT + c2] = pc[c2];
                }
            }
            __syncthreads();
            if (tid < DOUT) {
                float v = b2[tid];
                #pragma unroll
                for (int ww = 0; ww < 8; ww++) v += fin[ww * DOUT + tid];
                fin[96 + tid] = v;
            }
            __syncthreads();
            if (tid == 0) {
                float mx = fin[96];
                #pragma unroll
                for (int c2 = 1; c2 < DOUT; c2++) mx = fmaxf(mx, fin[96 + c2]);
                float se = 0.f;
                #pragma unroll
                for (int c2 = 0; c2 < DOUT; c2++) se += expf(fin[96 + c2] - mx);
                fin[110] = mx;
                fin[111] = logf(se);
            }
            __syncthreads();
            if (tid < DOUT)
                out[gph * DOUT + tid] = fin[96 + tid] - fin[110] - fin[111];
        }
        __syncthreads();
        t = sh_next;
    }
}

// ============================================================
extern "C" void kernel_launch(void* const* d_in, const int* in_sizes, int n_in,
                              void* d_out, int out_size) {
    const float* x  = (const float*)d_in[0];
    // d_in[1] = batch (int64) — sorted equal-sized graphs, not needed
    const float* W1 = (const float*)d_in[2];
    const float* b1 = (const float*)d_in[3];
    const float* W2 = (const float*)d_in[4];
    const float* b2 = (const float*)d_in[5];
    float* out = (float*)d_out;

    cudaFuncSetAttribute(k_gemm, cudaFuncAttributeMaxDynamicSharedMemorySize, SMEM_TOTAL);

    k_prep1<<<1040, 256>>>(x, W1);
    k_gemm<<<GRID_B, 512, SMEM_TOTAL>>>(x, b1, W2, b2, out);
}